// round 15
// baseline (speedup 1.0000x reference)
#include <cuda_runtime.h>

#define SDIM 7
#define NCELL 49
#define CH 30
#define NC 20
#define CONF_THR 0.25f
#define IOU_THR 0.45f
#define EPSF 1e-6f
#define NFLOAT (NCELL * CH)   // 1470
#define NVEC4 (NFLOAT / 4)    // 367 (tail of 2)
#define MASK49 ((1ull << NCELL) - 1ull)

__device__ __forceinline__ float fsig(float v) {
    return __fdividef(1.0f, 1.0f + __expf(-v));
}

__global__ void __launch_bounds__(64, 1)
yolo_decode_nms_kernel(const float4* __restrict__ x4,
                       const float* __restrict__ x,
                       float* __restrict__ out, int out_size) {
    __shared__ float4 xs4[NVEC4 + 1];
    __shared__ __align__(16) float conf[52];      // ORIG order, padded for float4 reads
    __shared__ int clsi[52];                      // ORIG order, padded for int4 reads
    __shared__ float4 geo4[NCELL];                // ORIG order: xmin, ymin, xmax, ymax
    __shared__ unsigned long long suppm[NCELL];   // keyed by rank; bits = ORIG index
    __shared__ unsigned long long selfb[NCELL];   // keyed by rank; 1<<orig_idx
    __shared__ unsigned long long nzmask;         // rank bits with nonzero supp
    __shared__ unsigned int bal[2];               // keep ballot, ORIG order

    float* xs = (float*)xs4;
    const int t = threadIdx.x;
    const int lane = t & 31;

    // ---- Phase 0: coalesced staging + pad init ----
    #pragma unroll
    for (int i = t; i < NVEC4; i += 64) xs4[i] = x4[i];
    if (t < 2) xs[NVEC4 * 4 + t] = x[NVEC4 * 4 + t];
    if (t < 3) { clsi[NCELL + t] = -1; conf[NCELL + t] = -1e30f; }
    if (t == 63) nzmask = 0ull;
    __syncthreads();   // barrier S

    // ---- Phase 1: decode own cell; conf/cls/geo written in ORIG order ----
    float fcls = 0.f, myconf = -1e30f, cx = 0.f, cy = 0.f, w = 0.f, h = 0.f;
    float xmin = 0.f, ymin = 0.f, xmax = 0.f, ymax = 0.f;
    int myclsi = -1;
    if (t < NCELL) {
        const float2* c = (const float2*)(xs + t * CH);  // t*120B from 16B base, 8B-aligned
        float r[CH];
        #pragma unroll
        for (int k = 0; k < CH / 2; k++) {
            const float2 v = c[k];
            r[2 * k] = v.x; r[2 * k + 1] = v.y;
        }

        float m01 = fmaxf(r[0], r[1]),   m23 = fmaxf(r[2], r[3]);
        float m45 = fmaxf(r[4], r[5]),   m67 = fmaxf(r[6], r[7]);
        float m89 = fmaxf(r[8], r[9]),   mab = fmaxf(r[10], r[11]);
        float mcd = fmaxf(r[12], r[13]), mef = fmaxf(r[14], r[15]);
        float mgh = fmaxf(r[16], r[17]), mij = fmaxf(r[18], r[19]);
        float q0 = fmaxf(m01, m23), q1 = fmaxf(m45, m67), q2 = fmaxf(m89, mab);
        float q3 = fmaxf(mcd, mef), q4 = fmaxf(mgh, mij);
        float mv = fmaxf(fmaxf(fmaxf(q0, q1), fmaxf(q2, q3)), q4);
        unsigned em = 0;
        #pragma unroll
        for (int i = 0; i < NC; i++) em |= (r[i] == mv) ? (1u << i) : 0u;
        myclsi = __ffs(em) - 1;       // first index wins ties
        fcls = (float)myclsi;

        const float c0 = r[NC + 0], c1 = r[NC + 5];
        const int bb = (c1 > c0) ? 1 : 0;   // box0 wins ties
        const int boff = NC + 5 * bb;
        myconf = fsig(fmaxf(c0, c1));
        const float bx = fsig(r[boff + 1]);
        const float by = fsig(r[boff + 2]);
        const float bw = fsig(r[boff + 3]);
        const float bh = fsig(r[boff + 4]);

        const int gy = t / SDIM;
        const int gx = t - gy * SDIM;
        const float stride = 448.0f / (float)SDIM;  // 64
        cx = (bx + (float)gx) * stride;
        cy = (by + (float)gy) * stride;
        w  = bw * (float)SDIM * stride;
        h  = bh * (float)SDIM * stride;

        conf[t] = myconf;
        clsi[t] = myclsi;
        xmin = cx - 0.5f * w; xmax = cx + 0.5f * w;
        ymin = cy - 0.5f * h; ymax = cy + 0.5f * h;
        geo4[t] = make_float4(xmin, ymin, xmax, ymax);
    }
    // keep0 bits in ORIG order (used directly for propagation)
    const unsigned kcbal = __ballot_sync(0xffffffffu, (t < NCELL) && (myconf > CONF_THR));
    if (lane == 0) bal[t >> 5] = kcbal;
    __syncthreads();   // barrier A: conf/clsi/geo4 (orig) + pads visible

    // ---- Phase 2: ONE pass -> lower-priority mask (lp) + same-class mask (sc);
    //      rank = 48 - popc(lp); suppression candidates = lp & sc; sparse IoU ----
    int rank = 0;
    if (t < NCELL) {
        unsigned long long lp = 0ull, sc = 0ull;
        const float4* cp4 = (const float4*)conf;
        const int4*   ci4 = (const int4*)clsi;
        #pragma unroll
        for (int q = 0; q < 13; q++) {
            const float4 cf = cp4[q];
            const int4   cw = ci4[q];
            const int j0 = 4 * q;
            // lower priority than me: (conf_j < mine) || (== && j > t). Self excluded.
            lp |= (unsigned long long)((cf.x < myconf) | ((cf.x == myconf) & ((j0 + 0) > t))) << (j0 + 0);
            lp |= (unsigned long long)((cf.y < myconf) | ((cf.y == myconf) & ((j0 + 1) > t))) << (j0 + 1);
            lp |= (unsigned long long)((cf.z < myconf) | ((cf.z == myconf) & ((j0 + 2) > t))) << (j0 + 2);
            lp |= (unsigned long long)((cf.w < myconf) | ((cf.w == myconf) & ((j0 + 3) > t))) << (j0 + 3);
            sc |= (unsigned long long)(cw.x == myclsi) << (j0 + 0);
            sc |= (unsigned long long)(cw.y == myclsi) << (j0 + 1);
            sc |= (unsigned long long)(cw.z == myclsi) << (j0 + 2);
            sc |= (unsigned long long)(cw.w == myclsi) << (j0 + 3);
        }
        lp &= MASK49;                                  // drop pad bits (pads have conf=-1e30)
        rank = (NCELL - 1) - __popcll(lp);             // #higher-priority
        unsigned long long cm = lp & sc;               // suppression candidates (orig idx)
        const float a_i = fabsf(w * h);
        unsigned long long m = 0ull;
        while (cm) {
            const int j = __ffsll((long long)cm) - 1;
            cm &= cm - 1ull;
            const float4 gj = geo4[j];
            const float iw = fmaxf(fminf(xmax, gj.z) - fmaxf(xmin, gj.x), 0.0f);
            const float ih = fmaxf(fminf(ymax, gj.w) - fmaxf(ymin, gj.y), 0.0f);
            const float inter = iw * ih;
            const float a_j = fabsf((gj.z - gj.x) * (gj.w - gj.y));
            if (inter >= IOU_THR * (a_i + a_j - inter + EPSF)) m |= (1ull << j);
        }
        if (m) {
            suppm[rank] = m;                   // orig-index bits, keyed by rank
            selfb[rank] = 1ull << t;
            atomicOr(&nzmask, 1ull << rank);   // rare (~0-3 threads)
        }
    }
    __syncthreads();   // barrier B: suppm/selfb/nzmask visible

    // ---- Phase 3: sparse sequential propagation (ascending rank, orig-space masks) ----
    unsigned long long keepm = (unsigned long long)bal[0] |
                               ((unsigned long long)bal[1] << 32);
    unsigned long long nz = nzmask;
    while (nz) {
        const int rr = __ffsll((long long)nz) - 1;
        nz &= nz - 1ull;
        if (keepm & selfb[rr]) keepm &= ~suppm[rr];
    }

    // ---- Output: register-direct, rank-addressed ----
    if (t < NCELL) {
        const float k = (float)((keepm >> t) & 1ull);
        float2* o2 = (float2*)(out + rank * 6);   // out 256B-aligned; rank*24B -> 8B-aligned
        o2[0] = make_float2(fcls * k, myconf * k);
        o2[1] = make_float2(cx * k, cy * k);
        o2[2] = make_float2(w * k, h * k);
        out[NCELL * 6 + rank] = k;
    }
}

extern "C" void kernel_launch(void* const* d_in, const int* in_sizes, int n_in,
                              void* d_out, int out_size) {
    const float* x = (const float*)d_in[0];
    float* out = (float*)d_out;
    yolo_decode_nms_kernel<<<1, 64>>>((const float4*)x, x, out, out_size);
}

// round 16
// speedup vs baseline: 1.0435x; 1.0435x over previous
#include <cuda_runtime.h>

#define SDIM 7
#define NCELL 49
#define CH 30
#define NC 20
#define CONF_THR 0.25f
#define IOU_THR 0.45f
#define EPSF 1e-6f
#define MASK49 ((1ull << NCELL) - 1ull)

__device__ __forceinline__ float fsig(float v) {
    return __fdividef(1.0f, 1.0f + __expf(-v));
}

__global__ void __launch_bounds__(64, 1)
yolo_decode_nms_kernel(const float2* __restrict__ x2,
                       float* __restrict__ out, int out_size) {
    __shared__ __align__(16) float conf[52];      // ORIG order, padded for float4 reads
    __shared__ int clsi[52];                      // ORIG order, padded for int4 reads
    __shared__ float4 geo4[NCELL];                // ORIG order: xmin, ymin, xmax, ymax
    __shared__ unsigned long long suppm[NCELL];   // keyed by rank; bits = ORIG index
    __shared__ unsigned long long selfb[NCELL];   // keyed by rank; 1<<orig_idx
    __shared__ unsigned long long nzmask;         // rank bits with nonzero supp
    __shared__ unsigned int bal[2];               // keep ballot, ORIG order

    const int t = threadIdx.x;
    const int lane = t & 31;

    // ---- Pad init (consumed only after barrier A / B respectively) ----
    if (t < 3) { clsi[NCELL + t] = -1; conf[NCELL + t] = -1e30f; }
    if (t == 63) nzmask = 0ull;

    // ---- Phase 1: decode own cell DIRECTLY from global (15x LDG.64, full MLP) ----
    float fcls = 0.f, myconf = -1e30f, cx = 0.f, cy = 0.f, w = 0.f, h = 0.f;
    float xmin = 0.f, ymin = 0.f, xmax = 0.f, ymax = 0.f;
    int myclsi = -1;
    if (t < NCELL) {
        const float2* c = x2 + t * (CH / 2);   // byte offset 120*t, 8B-aligned
        float r[CH];
        #pragma unroll
        for (int k = 0; k < CH / 2; k++) {
            const float2 v = c[k];
            r[2 * k] = v.x; r[2 * k + 1] = v.y;
        }

        float m01 = fmaxf(r[0], r[1]),   m23 = fmaxf(r[2], r[3]);
        float m45 = fmaxf(r[4], r[5]),   m67 = fmaxf(r[6], r[7]);
        float m89 = fmaxf(r[8], r[9]),   mab = fmaxf(r[10], r[11]);
        float mcd = fmaxf(r[12], r[13]), mef = fmaxf(r[14], r[15]);
        float mgh = fmaxf(r[16], r[17]), mij = fmaxf(r[18], r[19]);
        float q0 = fmaxf(m01, m23), q1 = fmaxf(m45, m67), q2 = fmaxf(m89, mab);
        float q3 = fmaxf(mcd, mef), q4 = fmaxf(mgh, mij);
        float mv = fmaxf(fmaxf(fmaxf(q0, q1), fmaxf(q2, q3)), q4);
        unsigned em = 0;
        #pragma unroll
        for (int i = 0; i < NC; i++) em |= (r[i] == mv) ? (1u << i) : 0u;
        myclsi = __ffs(em) - 1;       // first index wins ties
        fcls = (float)myclsi;

        const float c0 = r[NC + 0], c1 = r[NC + 5];
        const int bb = (c1 > c0) ? 1 : 0;   // box0 wins ties
        const int boff = NC + 5 * bb;
        myconf = fsig(fmaxf(c0, c1));
        const float bx = fsig(r[boff + 1]);
        const float by = fsig(r[boff + 2]);
        const float bw = fsig(r[boff + 3]);
        const float bh = fsig(r[boff + 4]);

        const int gy = t / SDIM;
        const int gx = t - gy * SDIM;
        const float stride = 448.0f / (float)SDIM;  // 64
        cx = (bx + (float)gx) * stride;
        cy = (by + (float)gy) * stride;
        w  = bw * (float)SDIM * stride;
        h  = bh * (float)SDIM * stride;

        conf[t] = myconf;
        clsi[t] = myclsi;
        xmin = cx - 0.5f * w; xmax = cx + 0.5f * w;
        ymin = cy - 0.5f * h; ymax = cy + 0.5f * h;
        geo4[t] = make_float4(xmin, ymin, xmax, ymax);
    }
    // keep0 bits in ORIG order (used directly for propagation)
    const unsigned kcbal = __ballot_sync(0xffffffffu, (t < NCELL) && (myconf > CONF_THR));
    if (lane == 0) bal[t >> 5] = kcbal;
    __syncthreads();   // barrier A: conf/clsi/geo4 (orig) + pads visible

    // ---- Phase 2: ONE pass -> lower-priority mask (lp) + same-class mask (sc);
    //      rank = 48 - popc(lp); suppression candidates = lp & sc; sparse IoU ----
    int rank = 0;
    if (t < NCELL) {
        unsigned long long lp = 0ull, sc = 0ull;
        const float4* cp4 = (const float4*)conf;
        const int4*   ci4 = (const int4*)clsi;
        #pragma unroll
        for (int q = 0; q < 13; q++) {
            const float4 cf = cp4[q];
            const int4   cw = ci4[q];
            const int j0 = 4 * q;
            // lower priority than me: (conf_j < mine) || (== && j > t). Self excluded.
            lp |= (unsigned long long)((cf.x < myconf) | ((cf.x == myconf) & ((j0 + 0) > t))) << (j0 + 0);
            lp |= (unsigned long long)((cf.y < myconf) | ((cf.y == myconf) & ((j0 + 1) > t))) << (j0 + 1);
            lp |= (unsigned long long)((cf.z < myconf) | ((cf.z == myconf) & ((j0 + 2) > t))) << (j0 + 2);
            lp |= (unsigned long long)((cf.w < myconf) | ((cf.w == myconf) & ((j0 + 3) > t))) << (j0 + 3);
            sc |= (unsigned long long)(cw.x == myclsi) << (j0 + 0);
            sc |= (unsigned long long)(cw.y == myclsi) << (j0 + 1);
            sc |= (unsigned long long)(cw.z == myclsi) << (j0 + 2);
            sc |= (unsigned long long)(cw.w == myclsi) << (j0 + 3);
        }
        lp &= MASK49;                                  // drop pad bits (pads have conf=-1e30)
        rank = (NCELL - 1) - __popcll(lp);             // #higher-priority
        unsigned long long cm = lp & sc;               // suppression candidates (orig idx)
        const float a_i = fabsf(w * h);
        unsigned long long m = 0ull;
        while (cm) {
            const int j = __ffsll((long long)cm) - 1;
            cm &= cm - 1ull;
            const float4 gj = geo4[j];
            const float iw = fmaxf(fminf(xmax, gj.z) - fmaxf(xmin, gj.x), 0.0f);
            const float ih = fmaxf(fminf(ymax, gj.w) - fmaxf(ymin, gj.y), 0.0f);
            const float inter = iw * ih;
            const float a_j = fabsf((gj.z - gj.x) * (gj.w - gj.y));
            if (inter >= IOU_THR * (a_i + a_j - inter + EPSF)) m |= (1ull << j);
        }
        if (m) {
            suppm[rank] = m;                   // orig-index bits, keyed by rank
            selfb[rank] = 1ull << t;
            atomicOr(&nzmask, 1ull << rank);   // rare (~0-3 threads)
        }
    }
    __syncthreads();   // barrier B: suppm/selfb/nzmask visible

    // ---- Phase 3: sparse sequential propagation (ascending rank, orig-space masks) ----
    unsigned long long keepm = (unsigned long long)bal[0] |
                               ((unsigned long long)bal[1] << 32);
    unsigned long long nz = nzmask;
    while (nz) {
        const int rr = __ffsll((long long)nz) - 1;
        nz &= nz - 1ull;
        if (keepm & selfb[rr]) keepm &= ~suppm[rr];
    }

    // ---- Output: register-direct, rank-addressed ----
    if (t < NCELL) {
        const float k = (float)((keepm >> t) & 1ull);
        float2* o2 = (float2*)(out + rank * 6);   // out 256B-aligned; rank*24B -> 8B-aligned
        o2[0] = make_float2(fcls * k, myconf * k);
        o2[1] = make_float2(cx * k, cy * k);
        o2[2] = make_float2(w * k, h * k);
        out[NCELL * 6 + rank] = k;
    }
}

extern "C" void kernel_launch(void* const* d_in, const int* in_sizes, int n_in,
                              void* d_out, int out_size) {
    const float* x = (const float*)d_in[0];
    float* out = (float*)d_out;
    yolo_decode_nms_kernel<<<1, 64>>>((const float2*)x, out, out_size);
}